// round 2
// baseline (speedup 1.0000x reference)
#include <cuda_runtime.h>
#include <cstdint>

// Problem constants
#define BB   512          // batch
#define SS   336          // encoder sequence length
#define INW  7            // encoder input width
#define HH   512          // hidden
#define TT   96           // decoder steps

#define NCTA 128          // persistent grid size (<= SM count, guaranteed co-resident)

typedef unsigned long long ull;

// ---------------------------------------------------------------------------
// Scratch (device globals; allocation is forbidden)
// ---------------------------------------------------------------------------
__device__ float g_h0a[BB * HH];
__device__ float g_h0b[BB * HH];
__device__ float g_c0 [BB * HH];
__device__ float g_h1a[BB * HH];
__device__ float g_h1b[BB * HH];
__device__ float g_c1 [BB * HH];
__device__ float g_enc[(size_t)BB * SS * HH];   // encoder outputs, 352 MB
__device__ float g_q  [BB * HH];
__device__ float g_ctx[BB * HH];
__device__ float g_cc [BB * HH];
__device__ float g_pred[BB];
__device__ unsigned g_bar_enc;
__device__ unsigned g_bar_dec;

// ---------------------------------------------------------------------------
// Packed fp32x2 FMA (Blackwell): 2 fp32 FMAs per instruction on the FMA pipe.
// ---------------------------------------------------------------------------
__device__ __forceinline__ ull pack2(float x, float y) {
    ull r; asm("mov.b64 %0, {%1, %2};" : "=l"(r) : "f"(x), "f"(y)); return r;
}
__device__ __forceinline__ float2 unpack2(ull v) {
    float2 r; asm("mov.b64 {%0, %1}, %2;" : "=f"(r.x), "=f"(r.y) : "l"(v)); return r;
}
__device__ __forceinline__ void fma2(ull& d, ull a, ull b) {
    asm("fma.rn.f32x2 %0, %1, %2, %0;" : "+l"(d) : "l"(a), "l"(b));
}

// ---------------------------------------------------------------------------
// Software grid barrier (persistent kernel, NCTA co-resident CTAs).
// Monotonic counter; reset by memset at each kernel_launch (graph replay safe).
// ---------------------------------------------------------------------------
__device__ __forceinline__ void gbar(unsigned* cnt, unsigned& target) {
    __threadfence();          // release: make this thread's writes visible
    __syncthreads();          // everyone in CTA fenced before arrival
    target += NCTA;
    if (threadIdx.x == 0) {
        atomicAdd(cnt, 1u);
        while (*(volatile unsigned*)cnt < target) { }
        __threadfence();      // acquire
    }
    __syncthreads();
}

// ---------------------------------------------------------------------------
// LSTM tile (device fn): one CTA computes a 64(batch) x 32(n) x 4(gate) tile.
// MODE 0: encoder layer 0 (x tail K=7)   MODE 1: encoder layer 1 (2nd GEMM pass,
// writes enc_out)                        MODE 2: decoder cell (rank-1 input)
// Cross-CTA-produced activations are loaded with .cg (L1 is stale within a
// persistent launch); weights/biases are safe to cache.
// smem layout: As[16][68] then Bs[4][16][34]
// ---------------------------------------------------------------------------
template<int MODE>
__device__ void lstm_tile(float* sm,
                          const float* __restrict__ hin,
                          const float* __restrict__ Whh,
                          const float* __restrict__ x2,
                          const float* __restrict__ Wih,
                          const float* __restrict__ bias,
                          float* __restrict__ hout,
                          float* __restrict__ c,
                          float* __restrict__ eout)
{
    float (*As)[68]     = (float(*)[68])sm;
    float (*Bs)[16][34] = (float(*)[16][34])(sm + 16 * 68);

    const int tid = threadIdx.x;
    const int tx  = tid & 15;             // n direction (x2)
    const int ty  = tid >> 4;             // m direction (x4)
    const int mBase = (blockIdx.x >> 4) * 64;   // 8 m-tiles
    const int nBase = (blockIdx.x & 15) * 32;   // 16 n-tiles

    ull acc2[4][4];
#pragma unroll
    for (int q = 0; q < 4; q++)
#pragma unroll
        for (int i = 0; i < 4; i++) acc2[q][i] = 0ull;

    const int npass = (MODE == 1) ? 2 : 1;
    for (int p = 0; p < npass; p++) {
        const float* A  = p ? x2  : hin;
        const float* Wp = p ? Wih : Whh;
        for (int k0 = 0; k0 < 512; k0 += 16) {
            {   // A tile 64x16, transposed into As[k][m], L2-coherent loads
                int m = tid >> 2, kc = tid & 3;
                float4 v = __ldcg((const float4*)(A + (size_t)(mBase + m) * 512 + k0 + kc * 4));
                As[kc * 4 + 0][m] = v.x;
                As[kc * 4 + 1][m] = v.y;
                As[kc * 4 + 2][m] = v.z;
                As[kc * 4 + 3][m] = v.w;
            }
#pragma unroll
            for (int it = 0; it < 2; it++) {   // B tiles: 4 gates x 32 rows x 16 k
                int l  = tid + it * 256;
                int q  = l >> 7;
                int r  = (l & 127) >> 2;
                int kc = l & 3;
                float4 v = *(const float4*)(Wp + (size_t)(q * 512 + nBase + r) * 512 + k0 + kc * 4);
                Bs[q][kc * 4 + 0][r] = v.x;
                Bs[q][kc * 4 + 1][r] = v.y;
                Bs[q][kc * 4 + 2][r] = v.z;
                Bs[q][kc * 4 + 3][r] = v.w;
            }
            __syncthreads();
#pragma unroll
            for (int k = 0; k < 16; k++) {
                ull av[4];
#pragma unroll
                for (int i = 0; i < 4; i++) { float a = As[k][ty * 4 + i]; av[i] = pack2(a, a); }
                ull bv[4];
#pragma unroll
                for (int q = 0; q < 4; q++) bv[q] = *(const ull*)&Bs[q][k][tx * 2];
#pragma unroll
                for (int q = 0; q < 4; q++)
#pragma unroll
                    for (int i = 0; i < 4; i++) fma2(acc2[q][i], av[i], bv[q]);
            }
            __syncthreads();
        }
    }

    float accf[4][4][2];
#pragma unroll
    for (int q = 0; q < 4; q++)
#pragma unroll
        for (int i = 0; i < 4; i++) {
            float2 v = unpack2(acc2[q][i]);
            accf[q][i][0] = v.x; accf[q][i][1] = v.y;
        }

    if (MODE == 0) {        // x tail: K2 = 7, x2 = x + t*INW, row stride SS*INW
        float xv[4][7];
#pragma unroll
        for (int i = 0; i < 4; i++)
#pragma unroll
            for (int k = 0; k < INW; k++)
                xv[i][k] = __ldg(x2 + (size_t)(mBase + ty * 4 + i) * (SS * INW) + k);
#pragma unroll
        for (int q = 0; q < 4; q++)
#pragma unroll
            for (int j = 0; j < 2; j++) {
                int n = nBase + tx * 2 + j;
#pragma unroll
                for (int k = 0; k < INW; k++) {
                    float w = __ldg(Wih + (size_t)(q * 512 + n) * INW + k);
#pragma unroll
                    for (int i = 0; i < 4; i++) accf[q][i][j] += xv[i][k] * w;
                }
            }
    }
    if (MODE == 2) {        // rank-1 input: pred[b] * W_ih[:,0]
        float di[4];
#pragma unroll
        for (int i = 0; i < 4; i++) di[i] = __ldcg(x2 + mBase + ty * 4 + i);
#pragma unroll
        for (int q = 0; q < 4; q++)
#pragma unroll
            for (int j = 0; j < 2; j++) {
                float w = __ldg(Wih + q * 512 + nBase + tx * 2 + j);
#pragma unroll
                for (int i = 0; i < 4; i++) accf[q][i][j] += di[i] * w;
            }
    }

#pragma unroll
    for (int i = 0; i < 4; i++)
#pragma unroll
        for (int j = 0; j < 2; j++) {
            int row = mBase + ty * 4 + i;
            int col = nBase + tx * 2 + j;
            int idx = row * 512 + col;
            float gi = accf[0][i][j] + bias[col];
            float gf = accf[1][i][j] + bias[512 + col];
            float gg = accf[2][i][j] + bias[1024 + col];
            float go = accf[3][i][j] + bias[1536 + col];
            float si = 1.f / (1.f + __expf(-gi));
            float sf = 1.f / (1.f + __expf(-gf));
            float so = 1.f / (1.f + __expf(-go));
            float cn = sf * c[idx] + si * tanhf(gg);
            float hn = so * tanhf(cn);
            c[idx]    = cn;     // owner-thread: same thread each step, L1-safe
            hout[idx] = hn;
            if (MODE == 1) eout[(size_t)row * (SS * HH) + col] = hn;
        }
}

// ---------------------------------------------------------------------------
// GEMM tile, BM=32 x BN=64, 128 tiles (full persistent grid busy):
//   out[b,n] = act( A1[b,:K1]·W[n,:K1] + A2[b,:K2]·W[n,K1:K1+K2] + bias[n] )
// smem: As[16][36] then Bs[16][68]
// ---------------------------------------------------------------------------
__device__ void gemm32_tile(float* sm,
                            const float* __restrict__ A1, int K1,
                            const float* __restrict__ A2, int K2,
                            const float* __restrict__ W,  int ldw,
                            const float* __restrict__ bias,
                            float* __restrict__ out, int act)
{
    float (*As)[36] = (float(*)[36])sm;
    float (*Bs)[68] = (float(*)[68])(sm + 16 * 36);

    const int tid = threadIdx.x;
    const int tx = tid & 15, ty = tid >> 4;
    const int mBase = (blockIdx.x >> 3) * 32;   // 16 m-tiles
    const int nBase = (blockIdx.x & 7) * 64;    // 8 n-tiles

    ull acc2[2][2] = {{0ull, 0ull}, {0ull, 0ull}};

    for (int part = 0; part < 2; part++) {
        const float* A = part ? A2 : A1;
        const int K    = part ? K2 : K1;
        const int coff = part ? K1 : 0;
        if (A == nullptr || K == 0) continue;
        for (int k0 = 0; k0 < K; k0 += 16) {
            {   int m = tid >> 3, kc = tid & 7;
                float2 v = __ldcg((const float2*)(A + (size_t)(mBase + m) * K + k0 + kc * 2));
                As[kc * 2 + 0][m] = v.x;
                As[kc * 2 + 1][m] = v.y;
            }
            {   int r = tid >> 2, kc = tid & 3;
                float4 v = *(const float4*)(W + (size_t)(nBase + r) * ldw + coff + k0 + kc * 4);
                Bs[kc * 4 + 0][r] = v.x;
                Bs[kc * 4 + 1][r] = v.y;
                Bs[kc * 4 + 2][r] = v.z;
                Bs[kc * 4 + 3][r] = v.w;
            }
            __syncthreads();
#pragma unroll
            for (int k = 0; k < 16; k++) {
                ull av[2];
#pragma unroll
                for (int i = 0; i < 2; i++) { float a = As[k][ty * 2 + i]; av[i] = pack2(a, a); }
                ull bv[2];
                bv[0] = *(const ull*)&Bs[k][tx * 4];
                bv[1] = *(const ull*)&Bs[k][tx * 4 + 2];
#pragma unroll
                for (int i = 0; i < 2; i++) {
                    fma2(acc2[i][0], av[i], bv[0]);
                    fma2(acc2[i][1], av[i], bv[1]);
                }
            }
            __syncthreads();
        }
    }

#pragma unroll
    for (int i = 0; i < 2; i++)
#pragma unroll
        for (int jp = 0; jp < 2; jp++) {
            float2 v = unpack2(acc2[i][jp]);
            int row = mBase + ty * 2 + i;
            int col = nBase + tx * 4 + jp * 2;
            float v0 = v.x + (bias ? bias[col] : 0.f);
            float v1 = v.y + (bias ? bias[col + 1] : 0.f);
            if (act) { v0 = tanhf(v0); v1 = tanhf(v1); }
            out[row * 512 + col]     = v0;
            out[row * 512 + col + 1] = v1;
        }
}

// ---------------------------------------------------------------------------
// Attention phase: each CTA handles 4 batch rows; one pass over enc
// (online softmax fused score+softmax+context). s-loop unrolled x2 for MLP.
// smem: qs[512] cs[512] ms[8] ds[8]
// ---------------------------------------------------------------------------
__device__ void attn_phase(float* sm,
                           const float* __restrict__ enc,
                           const float* __restrict__ q,
                           float* __restrict__ ctx)
{
    float* qs = sm;
    float* cs = sm + 512;
    float* ms = sm + 1024;
    float* ds = sm + 1032;

    const int tid  = threadIdx.x;
    const int warp = tid >> 5;
    const int lane = tid & 31;

    for (int bi = 0; bi < 4; bi++) {
        const int b = blockIdx.x * 4 + bi;
        qs[tid]       = __ldcg(&q[b * 512 + tid]);
        qs[tid + 256] = __ldcg(&q[b * 512 + tid + 256]);
        cs[tid]       = 0.f;
        cs[tid + 256] = 0.f;
        __syncthreads();

        float m = -1e30f, d = 0.f;
        float cacc[16];
#pragma unroll
        for (int k = 0; k < 16; k++) cacc[k] = 0.f;

        const float* base = enc + (size_t)b * SS * HH;
        for (int s0 = warp * 2; s0 < SS; s0 += 16) {
            const float* r0 = base + (size_t)s0 * 512;
            const float* r1 = r0 + 512;
            float4 v0[4], v1[4];
            float p0 = 0.f, p1 = 0.f;
#pragma unroll
            for (int ch = 0; ch < 4; ch++) {
                v0[ch] = __ldcs((const float4*)(r0 + ch * 128 + lane * 4));
                v1[ch] = __ldcs((const float4*)(r1 + ch * 128 + lane * 4));
            }
#pragma unroll
            for (int ch = 0; ch < 4; ch++) {
                float4 qv = *(const float4*)(qs + ch * 128 + lane * 4);
                p0 += v0[ch].x * qv.x + v0[ch].y * qv.y + v0[ch].z * qv.z + v0[ch].w * qv.w;
                p1 += v1[ch].x * qv.x + v1[ch].y * qv.y + v1[ch].z * qv.z + v1[ch].w * qv.w;
            }
#pragma unroll
            for (int o = 16; o; o >>= 1) {
                p0 += __shfl_xor_sync(0xffffffffu, p0, o);
                p1 += __shfl_xor_sync(0xffffffffu, p1, o);
            }
            // online update with row s0
            {
                float mn = fmaxf(m, p0);
                float sc = __expf(m - mn);
                float w  = __expf(p0 - mn);
                d = d * sc + w;
#pragma unroll
                for (int ch = 0; ch < 4; ch++) {
                    cacc[ch * 4 + 0] = cacc[ch * 4 + 0] * sc + w * v0[ch].x;
                    cacc[ch * 4 + 1] = cacc[ch * 4 + 1] * sc + w * v0[ch].y;
                    cacc[ch * 4 + 2] = cacc[ch * 4 + 2] * sc + w * v0[ch].z;
                    cacc[ch * 4 + 3] = cacc[ch * 4 + 3] * sc + w * v0[ch].w;
                }
                m = mn;
            }
            // online update with row s0+1
            {
                float mn = fmaxf(m, p1);
                float sc = __expf(m - mn);
                float w  = __expf(p1 - mn);
                d = d * sc + w;
#pragma unroll
                for (int ch = 0; ch < 4; ch++) {
                    cacc[ch * 4 + 0] = cacc[ch * 4 + 0] * sc + w * v1[ch].x;
                    cacc[ch * 4 + 1] = cacc[ch * 4 + 1] * sc + w * v1[ch].y;
                    cacc[ch * 4 + 2] = cacc[ch * 4 + 2] * sc + w * v1[ch].z;
                    cacc[ch * 4 + 3] = cacc[ch * 4 + 3] * sc + w * v1[ch].w;
                }
                m = mn;
            }
        }

        if (lane == 0) { ms[warp] = m; ds[warp] = d; }
        __syncthreads();

        float M = -1e30f;
#pragma unroll
        for (int w8 = 0; w8 < 8; w8++) M = fmaxf(M, ms[w8]);
        float D = 0.f;
#pragma unroll
        for (int w8 = 0; w8 < 8; w8++) D += ds[w8] * __expf(ms[w8] - M);

        float f = __expf(m - M);   // lane-uniform within warp
#pragma unroll
        for (int ch = 0; ch < 4; ch++) {
            atomicAdd(&cs[ch * 128 + lane * 4 + 0], cacc[ch * 4 + 0] * f);
            atomicAdd(&cs[ch * 128 + lane * 4 + 1], cacc[ch * 4 + 1] * f);
            atomicAdd(&cs[ch * 128 + lane * 4 + 2], cacc[ch * 4 + 2] * f);
            atomicAdd(&cs[ch * 128 + lane * 4 + 3], cacc[ch * 4 + 3] * f);
        }
        __syncthreads();

        float invD = 1.f / D;
        ctx[b * 512 + tid]       = cs[tid] * invD;
        ctx[b * 512 + tid + 256] = cs[tid + 256] * invD;
        __syncthreads();
    }
}

// ---------------------------------------------------------------------------
// fc phase: pred[b] = cc[b,:]·fc_W + fc_b; write d_out[b,t]. CTAs 0..63.
// ---------------------------------------------------------------------------
__device__ void fc_phase(const float* __restrict__ cc,
                         const float* __restrict__ fcW,
                         const float* __restrict__ fcb,
                         float* __restrict__ pred,
                         float* __restrict__ out, int t)
{
    if (blockIdx.x >= 64) return;
    const int warp = threadIdx.x >> 5;
    const int lane = threadIdx.x & 31;
    const int b = blockIdx.x * 8 + warp;
    float s = 0.f;
    for (int k = lane; k < 512; k += 32) s += __ldcg(&cc[b * 512 + k]) * fcW[k];
#pragma unroll
    for (int o = 16; o; o >>= 1) s += __shfl_xor_sync(0xffffffffu, s, o);
    if (lane == 0) {
        float p = s + fcb[0];
        pred[b] = p;
        out[b * TT + t] = p;
    }
}

// ---------------------------------------------------------------------------
// Persistent encoder: 336 steps x 2 layers, grid barrier between phases.
// ---------------------------------------------------------------------------
__global__ __launch_bounds__(256, 1)
void enc_persist(const float* __restrict__ x,
                 const float* __restrict__ Wih0, const float* __restrict__ Whh0, const float* __restrict__ b0,
                 const float* __restrict__ Wih1, const float* __restrict__ Whh1, const float* __restrict__ b1,
                 float* h0a, float* h0b, float* c0,
                 float* h1a, float* h1b, float* c1,
                 float* enc, unsigned* bar)
{
    __shared__ __align__(16) float sm[16 * 68 + 4 * 16 * 34];
    unsigned target = 0;
    for (int t = 0; t < SS; t++) {
        const float* h0in  = (t & 1) ? h0b : h0a;
        float*       h0out = (t & 1) ? h0a : h0b;
        lstm_tile<0>(sm, h0in, Whh0, x + t * INW, Wih0, b0, h0out, c0, nullptr);
        gbar(bar, target);
        const float* h1in  = (t & 1) ? h1b : h1a;
        float*       h1out = (t & 1) ? h1a : h1b;
        lstm_tile<1>(sm, h1in, Whh1, h0out, Wih1, b1, h1out, c1, enc + (size_t)t * HH);
        gbar(bar, target);
    }
}

// ---------------------------------------------------------------------------
// Persistent decoder: 96 steps x {lstm, q, attention, cat, fc}.
// ---------------------------------------------------------------------------
__global__ __launch_bounds__(256, 1)
void dec_persist(const float* __restrict__ dWih, const float* __restrict__ dWhh, const float* __restrict__ db,
                 const float* __restrict__ attW, const float* __restrict__ catW, const float* __restrict__ catb,
                 const float* __restrict__ fcW,  const float* __restrict__ fcb,
                 float* h1a, float* h1b, float* c1, const float* __restrict__ enc,
                 float* qbuf, float* ctx, float* cc, float* pred,
                 float* out, unsigned* bar)
{
    __shared__ __align__(16) float sm[16 * 68 + 4 * 16 * 34];
    unsigned target = 0;
    float* hd  = h1a;   // encoder's last step (t=335, odd) wrote h1a
    float* hd2 = h1b;
    for (int t = 0; t < TT; t++) {
        lstm_tile<2>(sm, hd, dWhh, pred, dWih, db, hd2, c1, nullptr);
        gbar(bar, target);
        gemm32_tile(sm, hd2, 512, nullptr, 0, attW, 512, nullptr, qbuf, 0);
        gbar(bar, target);
        attn_phase(sm, enc, qbuf, ctx);
        gbar(bar, target);
        gemm32_tile(sm, hd2, 512, ctx, 512, catW, 1024, catb, cc, 1);
        gbar(bar, target);
        fc_phase(cc, fcW, fcb, pred, out, t);
        gbar(bar, target);
        float* tmp = hd; hd = hd2; hd2 = tmp;
    }
}

__global__ void init_pred_kernel(const float* __restrict__ x, float* __restrict__ pred)
{
    int b = blockIdx.x * 256 + threadIdx.x;
    if (b < BB) pred[b] = x[(size_t)b * (SS * INW) + (SS - 1) * INW + (INW - 1)];
}

// ---------------------------------------------------------------------------
// Host driver — 5 graph nodes total (no 4MB upload-pool growth).
// ---------------------------------------------------------------------------
extern "C" void kernel_launch(void* const* d_in, const int* in_sizes, int n_in,
                              void* d_out, int out_size)
{
    const float* x     = (const float*)d_in[0];
    const float* Wih0  = (const float*)d_in[1];
    const float* Whh0  = (const float*)d_in[2];
    const float* b0    = (const float*)d_in[3];
    const float* Wih1  = (const float*)d_in[4];
    const float* Whh1  = (const float*)d_in[5];
    const float* b1    = (const float*)d_in[6];
    const float* dWih  = (const float*)d_in[7];
    const float* dWhh  = (const float*)d_in[8];
    const float* db    = (const float*)d_in[9];
    const float* attW  = (const float*)d_in[10];
    const float* catW  = (const float*)d_in[11];
    const float* catb  = (const float*)d_in[12];
    const float* fcW   = (const float*)d_in[13];
    const float* fcb   = (const float*)d_in[14];
    float* out = (float*)d_out;

    float *h0a, *h0b, *c0, *h1a, *h1b, *c1, *encp, *qp, *ctxp, *ccp, *predp;
    unsigned *barE, *barD;
    cudaGetSymbolAddress((void**)&h0a,  g_h0a);
    cudaGetSymbolAddress((void**)&h0b,  g_h0b);
    cudaGetSymbolAddress((void**)&c0,   g_c0);
    cudaGetSymbolAddress((void**)&h1a,  g_h1a);
    cudaGetSymbolAddress((void**)&h1b,  g_h1b);
    cudaGetSymbolAddress((void**)&c1,   g_c1);
    cudaGetSymbolAddress((void**)&encp, g_enc);
    cudaGetSymbolAddress((void**)&qp,   g_q);
    cudaGetSymbolAddress((void**)&ctxp, g_ctx);
    cudaGetSymbolAddress((void**)&ccp,  g_cc);
    cudaGetSymbolAddress((void**)&predp,g_pred);
    cudaGetSymbolAddress((void**)&barE, g_bar_enc);
    cudaGetSymbolAddress((void**)&barD, g_bar_dec);

    const size_t stateBytes = (size_t)BB * HH * sizeof(float);
    cudaMemsetAsync(h0a, 0, stateBytes);
    cudaMemsetAsync(c0,  0, stateBytes);
    cudaMemsetAsync(h1a, 0, stateBytes);
    cudaMemsetAsync(c1,  0, stateBytes);
    cudaMemsetAsync(barE, 0, sizeof(unsigned));
    cudaMemsetAsync(barD, 0, sizeof(unsigned));

    init_pred_kernel<<<2, 256>>>(x, predp);

    enc_persist<<<NCTA, 256>>>(x, Wih0, Whh0, b0, Wih1, Whh1, b1,
                               h0a, h0b, c0, h1a, h1b, c1, encp, barE);

    dec_persist<<<NCTA, 256>>>(dWih, dWhh, db, attW, catW, catb, fcW, fcb,
                               h1a, h1b, c1, encp, qp, ctxp, ccp, predp,
                               out, barD);
}

// round 5
// speedup vs baseline: 1.6403x; 1.6403x over previous
#include <cuda_runtime.h>
#include <cuda_bf16.h>
#include <cstdint>

#define BB 512
#define SS 336
#define INW 7
#define HH 512
#define TT 96
#define NCTA 128

typedef unsigned long long ull;
typedef __nv_bfloat16 bf16;

// ---------------- smem layout (bytes) ----------------
#define SM_BIAS0 0            // 64 f32
#define SM_BIAS1 256          // 64 f32
#define SM_XW    512          // 64*8 f32 (enc L0 Wih rows / dec Wih col)
#define SM_XS    2560         // 128*8 f32 (per-step x rows / pred)
#define SM_BUF   8192
#define OFF_AH   0            // 128 rows * 144B
#define OFF_AL   18432
#define OFF_BH   36864        // 64 rows * 144B
#define OFF_BL   46080
#define BUFSZ    55296
#define SMEM_DYN (SM_BUF + 2 * BUFSZ)   // 118784

// ---------------- device scratch ----------------
__device__ __align__(16) float g_c0 [BB * HH];
__device__ __align__(16) float g_c1 [BB * HH];
__device__ __align__(16) float g_enc[(size_t)BB * SS * HH];
__device__ __align__(16) float g_q  [BB * HH];
__device__ __align__(16) float g_ctx[BB * HH];
__device__ __align__(16) float g_cc [BB * HH];
__device__ __align__(16) float g_hd [BB * HH];
__device__ __align__(16) float g_pred[BB];
__device__ __align__(16) bf16  g_h0h[2][BB * HH];
__device__ __align__(16) bf16  g_h0l[2][BB * HH];
__device__ __align__(16) bf16  g_h1h[2][BB * HH];
__device__ __align__(16) bf16  g_h1l[2][BB * HH];
// reordered weights: [mat(4)][nt(32)][j(64)][k(512)], j = u*4+g, src row = g*512 + nt*16 + u
#define WR_ELEMS ((size_t)4 * 32 * 64 * 512)
__device__ __align__(16) bf16 g_wrh[WR_ELEMS];
__device__ __align__(16) bf16 g_wrl[WR_ELEMS];
__device__ unsigned g_bar_enc;
__device__ unsigned g_bar_dec;

// ---------------- PTX helpers ----------------
__device__ __forceinline__ uint32_t smem_u32(const void* p) {
    uint32_t a;
    asm("{ .reg .u64 t; cvta.to.shared.u64 t, %1; cvt.u32.u64 %0, t; }" : "=r"(a) : "l"(p));
    return a;
}
__device__ __forceinline__ void cpa_cg(uint32_t s, const void* g) {
    asm volatile("cp.async.cg.shared.global [%0], [%1], 16;" :: "r"(s), "l"(g));
}
__device__ __forceinline__ void cpa_commit() { asm volatile("cp.async.commit_group;"); }
template<int N>
__device__ __forceinline__ void cpa_wait() { asm volatile("cp.async.wait_group %0;" :: "n"(N)); }

__device__ __forceinline__ void ldm4(uint32_t* r, uint32_t a) {
    asm volatile("ldmatrix.sync.aligned.m8n8.x4.shared.b16 {%0,%1,%2,%3}, [%4];"
        : "=r"(r[0]), "=r"(r[1]), "=r"(r[2]), "=r"(r[3]) : "r"(a));
}
__device__ __forceinline__ void mma16816(float* d, const uint32_t* a, const uint32_t* b) {
    asm volatile("mma.sync.aligned.m16n8k16.row.col.f32.bf16.bf16.f32 "
        "{%0,%1,%2,%3}, {%4,%5,%6,%7}, {%8,%9}, {%0,%1,%2,%3};"
        : "+f"(d[0]), "+f"(d[1]), "+f"(d[2]), "+f"(d[3])
        : "r"(a[0]), "r"(a[1]), "r"(a[2]), "r"(a[3]), "r"(b[0]), "r"(b[1]));
}

__device__ __forceinline__ ull pack2(float x, float y) {
    ull r; asm("mov.b64 %0, {%1, %2};" : "=l"(r) : "f"(x), "f"(y)); return r;
}
__device__ __forceinline__ float2 unpack2(ull v) {
    float2 r; asm("mov.b64 {%0, %1}, %2;" : "=f"(r.x), "=f"(r.y) : "l"(v)); return r;
}
__device__ __forceinline__ void fma2(ull& d, ull a, ull b) {
    asm("fma.rn.f32x2 %0, %1, %2, %0;" : "+l"(d) : "l"(a), "l"(b));
}

__device__ __forceinline__ void gbar(unsigned* cnt, unsigned& target) {
    __threadfence();
    __syncthreads();
    target += NCTA;
    if (threadIdx.x == 0) {
        atomicAdd(cnt, 1u);
        while (*(volatile unsigned*)cnt < target) { }
        __threadfence();
    }
    __syncthreads();
}

// ---------------- MMA LSTM step ----------------
// CTA tile: 128 batch x 64 gate-cols (16 hidden units, gates interleaved j=u*4+g)
// 8 warps = 4m x 2n, warp tile 32x32. K=512 per matrix, chunks of 64, dbl-buffered.

__device__ __forceinline__ void load_chunk(uint32_t sbase, int ch,
                                           const bf16* A_h, const bf16* A_l,
                                           const bf16* W_h, const bf16* W_l,
                                           int mBase, int tid)
{
    const int k0 = (ch & 7) * 64;
    const uint32_t sbuf = sbase + SM_BUF + (ch & 1) * BUFSZ;
#pragma unroll
    for (int i = 0; i < 4; i++) {
        int idx = tid + i * 256;
        int row = idx >> 3, cg = idx & 7;
        uint32_t so = row * 144 + cg * 16;
        size_t go = (size_t)(mBase + row) * 512 + k0 + cg * 8;
        cpa_cg(sbuf + OFF_AH + so, A_h + go);
        cpa_cg(sbuf + OFF_AL + so, A_l + go);
    }
#pragma unroll
    for (int i = 0; i < 2; i++) {
        int idx = tid + i * 256;
        int row = idx >> 3, cg = idx & 7;
        uint32_t so = row * 144 + cg * 16;
        size_t go = (size_t)row * 512 + k0 + cg * 8;
        cpa_cg(sbuf + OFF_BH + so, W_h + go);
        cpa_cg(sbuf + OFF_BL + so, W_l + go);
    }
    cpa_commit();
}

__device__ __forceinline__ void compute_chunk(uint32_t sbuf, float acc[2][4][4],
                                              int lane, int wm, int wn)
{
    const int q = lane >> 3, r = lane & 7;
    const uint32_t aOff = (uint32_t)(wm * 32 + (q & 1) * 8 + r) * 144 + ((q >> 1) * 8) * 2;
    const uint32_t bOff = (uint32_t)(wn * 32 + (q >> 1) * 8 + r) * 144 + ((q & 1) * 8) * 2;
    const uint32_t sAH = sbuf + OFF_AH, sAL = sbuf + OFF_AL;
    const uint32_t sBH = sbuf + OFF_BH, sBL = sbuf + OFF_BL;
#pragma unroll
    for (int ks = 0; ks < 4; ks++) {
        const uint32_t kb = ks * 32;           // 16 bf16 = 32 bytes
        uint32_t ah[2][4], al[2][4], bh[4][2], bl[4][2], t4[4];
        ldm4(ah[0], sAH + aOff + kb);
        ldm4(ah[1], sAH + aOff + 16 * 144 + kb);
        ldm4(al[0], sAL + aOff + kb);
        ldm4(al[1], sAL + aOff + 16 * 144 + kb);
        ldm4(t4, sBH + bOff + kb);
        bh[0][0] = t4[0]; bh[0][1] = t4[1]; bh[1][0] = t4[2]; bh[1][1] = t4[3];
        ldm4(t4, sBH + bOff + 16 * 144 + kb);
        bh[2][0] = t4[0]; bh[2][1] = t4[1]; bh[3][0] = t4[2]; bh[3][1] = t4[3];
        ldm4(t4, sBL + bOff + kb);
        bl[0][0] = t4[0]; bl[0][1] = t4[1]; bl[1][0] = t4[2]; bl[1][1] = t4[3];
        ldm4(t4, sBL + bOff + 16 * 144 + kb);
        bl[2][0] = t4[0]; bl[2][1] = t4[1]; bl[3][0] = t4[2]; bl[3][1] = t4[3];
#pragma unroll
        for (int fm = 0; fm < 2; fm++)
#pragma unroll
            for (int fn = 0; fn < 4; fn++) {
                mma16816(acc[fm][fn], ah[fm], bh[fn]);
                mma16816(acc[fm][fn], ah[fm], bl[fn]);
                mma16816(acc[fm][fn], al[fm], bh[fn]);
            }
    }
}

// MODE 0: enc layer0 (x tail K=7), MODE 1: enc layer1 (+enc_out), MODE 2: decoder (+g_hd)
template<int MODE>
__device__ void lstm_step(char* sm, int nmat,
                          const bf16* Ah0, const bf16* Al0, const bf16* Wh0, const bf16* Wl0,
                          const bf16* Ah1, const bf16* Al1, const bf16* Wh1, const bf16* Wl1,
                          int mBase, int nt, int t,
                          const float* __restrict__ x,
                          const float* __restrict__ pred,
                          int bias_off,
                          float* __restrict__ cst,
                          bf16* __restrict__ hH, bf16* __restrict__ hL,
                          float* __restrict__ fout)
{
    const int tid = threadIdx.x;
    const int lane = tid & 31, wid = tid >> 5;
    const int wm = wid >> 1, wn = wid & 1;
    const uint32_t sbase = smem_u32(sm);
    float* xs = (float*)(sm + SM_XS);

    // per-step epilogue inputs into smem
    if (MODE == 0) {
        for (int idx = tid; idx < 1024; idx += 256) {
            int row = idx >> 3, k = idx & 7;
            if (k < INW)
                xs[idx] = __ldg(x + (size_t)(mBase + row) * (SS * INW) + t * INW + k);
        }
    }
    if (MODE == 2) {
        if (tid < 128) xs[tid] = __ldcg(pred + mBase + tid);
    }

    float acc[2][4][4];
#pragma unroll
    for (int i = 0; i < 2; i++)
#pragma unroll
        for (int j = 0; j < 4; j++)
#pragma unroll
            for (int k = 0; k < 4; k++) acc[i][j][k] = 0.f;

    const int nch = nmat * 8;
    load_chunk(sbase, 0, Ah0, Al0, Wh0, Wl0, mBase, tid);
    for (int c = 0; c < nch; c++) {
        if (c + 1 < nch) {
            const int m1 = (c + 1) >> 3;
            load_chunk(sbase, c + 1, m1 ? Ah1 : Ah0, m1 ? Al1 : Al0,
                       m1 ? Wh1 : Wh0, m1 ? Wl1 : Wl0, mBase, tid);
            cpa_wait<1>();
        } else {
            cpa_wait<0>();
        }
        __syncthreads();
        compute_chunk(sbase + SM_BUF + (c & 1) * BUFSZ, acc, lane, wm, wn);
        __syncthreads();
    }

    // ---- epilogue: assemble gates via lane pairing, update c/h ----
    const float* bias = (const float*)(sm + bias_off);
    const float* xw = (const float*)(sm + SM_XW);
    const int rr = lane >> 2, cp = lane & 3, p = cp & 1;
#pragma unroll
    for (int fm = 0; fm < 2; fm++)
#pragma unroll
        for (int fn = 0; fn < 4; fn++) {
            float v0 = acc[fm][fn][0], v1 = acc[fm][fn][1];
            float v2 = acc[fm][fn][2], v3 = acc[fm][fn][3];
            float w0 = __shfl_xor_sync(0xffffffffu, v0, 1);
            float w1 = __shfl_xor_sync(0xffffffffu, v1, 1);
            float w2 = __shfl_xor_sync(0xffffffffu, v2, 1);
            float w3 = __shfl_xor_sync(0xffffffffu, v3, 1);
            const int ul = wn * 8 + fn * 2 + (cp >> 1);       // 0..15
            const int b = mBase + wm * 32 + fm * 16 + rr + (p ? 8 : 0);
            float gi, gf, gg, go;
            if (p == 0) { gi = v0; gf = v1; gg = w0; go = w1; }
            else        { gi = w2; gf = w3; gg = v2; go = v3; }
            const int j0 = ul * 4;
            gi += bias[j0 + 0];
            gf += bias[j0 + 1];
            gg += bias[j0 + 2];
            go += bias[j0 + 3];
            if (MODE == 0) {
                const float* xr = xs + (b - mBase) * 8;
#pragma unroll
                for (int k = 0; k < INW; k++) {
                    float xv = xr[k];
                    gi += xv * xw[(j0 + 0) * 8 + k];
                    gf += xv * xw[(j0 + 1) * 8 + k];
                    gg += xv * xw[(j0 + 2) * 8 + k];
                    go += xv * xw[(j0 + 3) * 8 + k];
                }
            }
            if (MODE == 2) {
                float pb = xs[b - mBase];
                gi += pb * xw[j0 + 0];
                gf += pb * xw[j0 + 1];
                gg += pb * xw[j0 + 2];
                go += pb * xw[j0 + 3];
            }
            const int hid = nt * 16 + ul;
            const int idx = b * 512 + hid;
            float si = 1.f / (1.f + __expf(-gi));
            float sf = 1.f / (1.f + __expf(-gf));
            float so = 1.f / (1.f + __expf(-go));
            float cn = sf * cst[idx] + si * tanhf(gg);
            float hn = so * tanhf(cn);
            cst[idx] = cn;
            bf16 hh = __float2bfloat16(hn);
            hH[idx] = hh;
            hL[idx] = __float2bfloat16(hn - __bfloat162float(hh));
            if (MODE == 1) fout[(size_t)b * (SS * HH) + hid] = hn;   // fout = g_enc + t*HH
            if (MODE == 2) fout[idx] = hn;                            // fout = g_hd
        }
}

// ---------------- SIMT decoder pieces (proven R2) ----------------
__device__ void gemm32_tile(float* sm,
                            const float* __restrict__ A1, int K1,
                            const float* __restrict__ A2, int K2,
                            const float* __restrict__ W, int ldw,
                            const float* __restrict__ bias,
                            float* __restrict__ out, int act)
{
    float (*As)[36] = (float(*)[36])sm;
    float (*Bs)[68] = (float(*)[68])(sm + 16 * 36);
    const int tid = threadIdx.x;
    const int tx = tid & 15, ty = tid >> 4;
    const int mBase = ((int)blockIdx.x >> 3) * 32;
    const int nBase = ((int)blockIdx.x & 7) * 64;
    ull acc2[2][2] = {{0ull, 0ull}, {0ull, 0ull}};
    for (int part = 0; part < 2; part++) {
        const float* A = part ? A2 : A1;
        const int K = part ? K2 : K1;
        const int coff = part ? K1 : 0;
        if (A == nullptr || K == 0) continue;
        for (int k0 = 0; k0 < K; k0 += 16) {
            {   int m = tid >> 3, kc = tid & 7;
                float2 v = __ldcg((const float2*)(A + (size_t)(mBase + m) * K + k0 + kc * 2));
                As[kc * 2 + 0][m] = v.x;
                As[kc * 2 + 1][m] = v.y;
            }
            {   int rr = tid >> 2, kc = tid & 3;
                float4 v = *(const float4*)(W + (size_t)(nBase + rr) * ldw + coff + k0 + kc * 4);
                Bs[kc * 4 + 0][rr] = v.x;
                Bs[kc * 4 + 1][rr] = v.y;
                Bs[kc * 4 + 2][rr] = v.z;
                Bs[kc * 4 + 3][rr] = v.w;
            }
            __syncthreads();
#pragma unroll
            for (int k = 0; k < 16; k++) {
                ull av[2];
#pragma unroll
                for (int i = 0; i < 2; i++) { float a = As[k][ty * 2 + i]; av[i] = pack2(a, a); }
                ull bv0 = *(const ull*)&Bs[k][tx * 4];
                ull bv1 = *(const ull*)&Bs[k][tx * 4 + 2];
#pragma unroll
                for (int i = 0; i < 2; i++) { fma2(acc2[i][0], av[i], bv0); fma2(acc2[i][1], av[i], bv1); }
            }
            __syncthreads();
        }
    }
#pragma unroll
    for (int i = 0; i < 2; i++)
#pragma unroll
        for (int jp = 0; jp < 2; jp++) {
            float2 v = unpack2(acc2[i][jp]);
            int row = mBase + ty * 2 + i;
            int col = nBase + tx * 4 + jp * 2;
            float v0 = v.x + (bias ? bias[col] : 0.f);
            float v1 = v.y + (bias ? bias[col + 1] : 0.f);
            if (act) { v0 = tanhf(v0); v1 = tanhf(v1); }
            out[row * 512 + col] = v0;
            out[row * 512 + col + 1] = v1;
        }
}

__device__ void attn_phase(float* sm, const float* __restrict__ enc,
                           const float* __restrict__ q, float* __restrict__ ctx)
{
    float* qs = sm; float* cs = sm + 512; float* ms = sm + 1024; float* ds = sm + 1032;
    const int tid = threadIdx.x, warp = tid >> 5, lane = tid & 31;
    for (int bi = 0; bi < 4; bi++) {
        const int b = (int)blockIdx.x * 4 + bi;
        qs[tid] = __ldcg(&q[b * 512 + tid]);
        qs[tid + 256] = __ldcg(&q[b * 512 + tid + 256]);
        cs[tid] = 0.f; cs[tid + 256] = 0.f;
        __syncthreads();
        float m = -1e30f, d = 0.f;
        float cacc[16];
#pragma unroll
        for (int k = 0; k < 16; k++) cacc[k] = 0.f;
        const float* base = enc + (size_t)b * SS * HH;
        for (int s0 = warp * 2; s0 < SS; s0 += 16) {
            const float* r0 = base + (size_t)s0 * 512;
            const float* r1 = r0 + 512;
            float4 v0[4], v1[4];
            float p0 = 0.f, p1 = 0.f;
#pragma unroll
            for (int ch = 0; ch < 4; ch++) {
                v0[ch] = __ldcs((const float4*)(r0 + ch * 128 + lane * 4));
                v1[ch] = __ldcs((const float4*)(r1 + ch * 128 + lane * 4));
            }
#pragma unroll
            for (int ch = 0; ch < 4; ch++) {
                float4 qv = *(const float4*)(qs + ch * 128 + lane * 4);
                p0 += v0[ch].x * qv.x + v0[ch].y * qv.y + v0[ch].z * qv.z + v0[ch].w * qv.w;
                p1 += v1[ch].x * qv.x + v1[ch].y * qv.y + v1[ch].z * qv.z + v1[ch].w * qv.w;
            }
#pragma unroll
            for (int o = 16; o; o >>= 1) {
                p0 += __shfl_xor_sync(0xffffffffu, p0, o);
                p1 += __shfl_xor_sync(0xffffffffu, p1, o);
            }
            {   float mn = fmaxf(m, p0);
                float sc = __expf(m - mn), w = __expf(p0 - mn);
                d = d * sc + w;
#pragma unroll
                for (int ch = 0; ch < 4; ch++) {
                    cacc[ch*4+0] = cacc[ch*4+0]*sc + w*v0[ch].x;
                    cacc[ch*4+1] = cacc[ch*4+1]*sc + w*v0[ch].y;
                    cacc[ch*4+2] = cacc[ch*4+2]*sc + w*v0[ch].z;
                    cacc[ch*4+3] = cacc[ch*4+3]*sc + w*v0[ch].w;
                }
                m = mn;
            }
            {   float mn = fmaxf(m, p1);
                float sc = __expf(m - mn), w = __expf(p1 - mn);
                d = d * sc + w;
#pragma unroll
                for (int ch = 0; ch < 4; ch++) {
                    cacc[ch*4+0] = cacc[ch*4+0]*sc + w*v1[ch].x;
                    cacc[ch*4+1] = cacc[ch*4+1]*sc + w*v1[ch].y;
                    cacc[ch*4+2] = cacc[ch*4+2]*sc + w*v1[ch].z;
                    cacc[ch*4+3] = cacc[ch*4+3]*sc + w*v1[ch].w;
                }
                m = mn;
            }
        }
        if (lane == 0) { ms[warp] = m; ds[warp] = d; }
        __syncthreads();
        float M = -1e30f;
#pragma unroll
        for (int w8 = 0; w8 < 8; w8++) M = fmaxf(M, ms[w8]);
        float D = 0.f;
#pragma unroll
        for (int w8 = 0; w8 < 8; w8++) D += ds[w8] * __expf(ms[w8] - M);
        float f = __expf(m - M);
#pragma unroll
        for (int ch = 0; ch < 4; ch++) {
            atomicAdd(&cs[ch*128 + lane*4 + 0], cacc[ch*4+0] * f);
            atomicAdd(&cs[ch*128 + lane*4 + 1], cacc[ch*4+1] * f);
            atomicAdd(&cs[ch*128 + lane*4 + 2], cacc[ch*4+2] * f);
            atomicAdd(&cs[ch*128 + lane*4 + 3], cacc[ch*4+3] * f);
        }
        __syncthreads();
        float invD = 1.f / D;
        ctx[b * 512 + tid] = cs[tid] * invD;
        ctx[b * 512 + tid + 256] = cs[tid + 256] * invD;
        __syncthreads();
    }
}

__device__ void fc_phase(const float* __restrict__ cc, const float* __restrict__ fcW,
                         const float* __restrict__ fcb, float* __restrict__ pred,
                         float* __restrict__ out, int t)
{
    if (blockIdx.x >= 64) return;
    const int warp = threadIdx.x >> 5, lane = threadIdx.x & 31;
    const int b = blockIdx.x * 8 + warp;
    float s = 0.f;
    for (int k = lane; k < 512; k += 32) s += __ldcg(&cc[b * 512 + k]) * fcW[k];
#pragma unroll
    for (int o = 16; o; o >>= 1) s += __shfl_xor_sync(0xffffffffu, s, o);
    if (lane == 0) { float p = s + fcb[0]; pred[b] = p; out[b * TT + t] = p; }
}

// ---------------- prep kernels ----------------
__global__ void prep_weights(const float* __restrict__ Whh0, const float* __restrict__ Whh1,
                             const float* __restrict__ Wih1, const float* __restrict__ dWhh)
{
    const float* mats[4] = {Whh0, Whh1, Wih1, dWhh};
    for (size_t i = (size_t)blockIdx.x * 256 + threadIdx.x; i < WR_ELEMS;
         i += (size_t)gridDim.x * 256) {
        int k  = (int)(i & 511);
        int j  = (int)((i >> 9) & 63);
        int nt = (int)((i >> 15) & 31);
        int m  = (int)(i >> 20);
        int row = (j & 3) * 512 + nt * 16 + (j >> 2);
        float v = __ldg(mats[m] + (size_t)row * 512 + k);
        bf16 h = __float2bfloat16(v);
        g_wrh[i] = h;
        g_wrl[i] = __float2bfloat16(v - __bfloat162float(h));
    }
}

__global__ void init_pred_kernel(const float* __restrict__ x, float* __restrict__ pred)
{
    int b = blockIdx.x * 256 + threadIdx.x;
    if (b < BB) pred[b] = x[(size_t)b * (SS * INW) + (SS - 1) * INW + (INW - 1)];
}

// ---------------- persistent encoder ----------------
__global__ __launch_bounds__(256, 1)
void enc_persist(const float* __restrict__ x, const float* __restrict__ Wih0,
                 const float* __restrict__ b0, const float* __restrict__ b1,
                 unsigned* bar)
{
    extern __shared__ __align__(16) char sm[];
    const int tid = threadIdx.x;
    const int mBase = ((int)blockIdx.x >> 5) * 128;
    const int nt = (int)blockIdx.x & 31;

    float* bias0 = (float*)(sm + SM_BIAS0);
    float* bias1 = (float*)(sm + SM_BIAS1);
    float* xw    = (float*)(sm + SM_XW);
    if (tid < 64) {
        int j = tid, row = (j & 3) * 512 + nt * 16 + (j >> 2);
        bias0[j] = __ldg(b0 + row);
        bias1[j] = __ldg(b1 + row);
        for (int k = 0; k < INW; k++) xw[j * 8 + k] = __ldg(Wih0 + (size_t)row * INW + k);
    }
    __syncthreads();

    const size_t tsz = (size_t)64 * 512;
    const bf16* w0h = g_wrh + (size_t)(0 * 32 + nt) * tsz;
    const bf16* w0l = g_wrl + (size_t)(0 * 32 + nt) * tsz;
    const bf16* w1h = g_wrh + (size_t)(1 * 32 + nt) * tsz;
    const bf16* w1l = g_wrl + (size_t)(1 * 32 + nt) * tsz;
    const bf16* w2h = g_wrh + (size_t)(2 * 32 + nt) * tsz;
    const bf16* w2l = g_wrl + (size_t)(2 * 32 + nt) * tsz;

    unsigned target = 0;
    for (int t = 0; t < SS; t++) {
        const int rp = t & 1, wp = 1 - rp;
        // layer 0: h0 @ Whh0^T (+x tail)
        lstm_step<0>(sm, 1,
                     g_h0h[rp], g_h0l[rp], w0h, w0l,
                     nullptr, nullptr, nullptr, nullptr,
                     mBase, nt, t, x, nullptr, SM_BIAS0,
                     g_c0, g_h0h[wp], g_h0l[wp], nullptr);
        gbar(bar, target);
        // layer 1: h1 @ Whh1^T + y0 @ Wih1^T
        lstm_step<1>(sm, 2,
                     g_h1h[rp], g_h1l[rp], w1h, w1l,
                     g_h0h[wp], g_h0l[wp], w2h, w2l,
                     mBase, nt, t, nullptr, nullptr, SM_BIAS1,
                     g_c1, g_h1h[wp], g_h1l[wp], g_enc + (size_t)t * HH);
        gbar(bar, target);
    }
}

// ---------------- persistent decoder ----------------
__global__ __launch_bounds__(256, 1)
void dec_persist(const float* __restrict__ dWih, const float* __restrict__ db,
                 const float* __restrict__ attW, const float* __restrict__ catW,
                 const float* __restrict__ catb, const float* __restrict__ fcW,
                 const float* __restrict__ fcb, float* __restrict__ out, unsigned* bar)
{
    extern __shared__ __align__(16) char sm[];
    const int tid = threadIdx.x;
    const int mBase = ((int)blockIdx.x >> 5) * 128;
    const int nt = (int)blockIdx.x & 31;

    float* bias0 = (float*)(sm + SM_BIAS0);
    float* xw    = (float*)(sm + SM_XW);
    if (tid < 64) {
        int j = tid, row = (j & 3) * 512 + nt * 16 + (j >> 2);
        bias0[j] = __ldg(db + row);
        xw[j] = __ldg(dWih + row);      // dec_W_ih is [2048,1]
    }
    __syncthreads();

    const size_t tsz = (size_t)64 * 512;
    const bf16* dwh = g_wrh + (size_t)(3 * 32 + nt) * tsz;
    const bf16* dwl = g_wrl + (size_t)(3 * 32 + nt) * tsz;

    unsigned target = 0;
    for (int t = 0; t < TT; t++) {
        const int rp = t & 1, wp = 1 - rp;
        lstm_step<2>(sm, 1,
                     g_h1h[rp], g_h1l[rp], dwh, dwl,
                     nullptr, nullptr, nullptr, nullptr,
                     mBase, nt, t, nullptr, g_pred, SM_BIAS0,
                     g_c1, g_h1h[wp], g_h1l[wp], g_hd);
        gbar(bar, target);
        gemm32_tile((float*)(sm + SM_BUF), g_hd, 512, nullptr, 0, attW, 512, nullptr, g_q, 0);
        gbar(bar, target);
        attn_phase((float*)(sm + SM_BUF), g_enc, g_q, g_ctx);
        gbar(bar, target);
        gemm32_tile((float*)(sm + SM_BUF), g_hd, 512, g_ctx, 512, catW, 1024, catb, g_cc, 1);
        gbar(bar, target);
        fc_phase(g_cc, fcW, fcb, g_pred, out, t);
        gbar(bar, target);
    }
}

// ---------------- host ----------------
extern "C" void kernel_launch(void* const* d_in, const int* in_sizes, int n_in,
                              void* d_out, int out_size)
{
    const float* x    = (const float*)d_in[0];
    const float* Wih0 = (const float*)d_in[1];
    const float* Whh0 = (const float*)d_in[2];
    const float* b0   = (const float*)d_in[3];
    const float* Wih1 = (const float*)d_in[4];
    const float* Whh1 = (const float*)d_in[5];
    const float* b1   = (const float*)d_in[6];
    const float* dWih = (const float*)d_in[7];
    const float* dWhh = (const float*)d_in[8];
    const float* db   = (const float*)d_in[9];
    const float* attW = (const float*)d_in[10];
    const float* catW = (const float*)d_in[11];
    const float* catb = (const float*)d_in[12];
    const float* fcW  = (const float*)d_in[13];
    const float* fcb  = (const float*)d_in[14];
    float* out = (float*)d_out;

    static int once = 0;
    if (!once) {
        cudaFuncSetAttribute(enc_persist, cudaFuncAttributeMaxDynamicSharedMemorySize, SMEM_DYN);
        cudaFuncSetAttribute(dec_persist, cudaFuncAttributeMaxDynamicSharedMemorySize, SMEM_DYN);
        once = 1;
    }

    float *c0p, *c1p, *predp;
    bf16 *h0hp, *h0lp, *h1hp, *h1lp;
    unsigned *barE, *barD;
    cudaGetSymbolAddress((void**)&c0p,  g_c0);
    cudaGetSymbolAddress((void**)&c1p,  g_c1);
    cudaGetSymbolAddress((void**)&predp,g_pred);
    cudaGetSymbolAddress((void**)&h0hp, g_h0h);
    cudaGetSymbolAddress((void**)&h0lp, g_h0l);
    cudaGetSymbolAddress((void**)&h1hp, g_h1h);
    cudaGetSymbolAddress((void**)&h1lp, g_h1l);
    cudaGetSymbolAddress((void**)&barE, g_bar_enc);
    cudaGetSymbolAddress((void**)&barD, g_bar_dec);

    const size_t sf = (size_t)BB * HH * sizeof(float);
    const size_t sh2 = (size_t)2 * BB * HH * sizeof(bf16);
    cudaMemsetAsync(c0p, 0, sf);
    cudaMemsetAsync(c1p, 0, sf);
    cudaMemsetAsync(h0hp, 0, sh2);
    cudaMemsetAsync(h0lp, 0, sh2);
    cudaMemsetAsync(h1hp, 0, sh2);
    cudaMemsetAsync(h1lp, 0, sh2);
    cudaMemsetAsync(barE, 0, sizeof(unsigned));
    cudaMemsetAsync(barD, 0, sizeof(unsigned));

    prep_weights<<<1024, 256>>>(Whh0, Whh1, Wih1, dWhh);
    init_pred_kernel<<<2, 256>>>(x, predp);

    enc_persist<<<NCTA, 256, SMEM_DYN>>>(x, Wih0, b0, b1, barE);
    dec_persist<<<NCTA, 256, SMEM_DYN>>>(dWih, db, attW, catW, catb, fcW, fcb, out, barD);
}